// round 3
// baseline (speedup 1.0000x reference)
#include <cuda_runtime.h>
#include <cstdint>

#define TAU_F 0.5f

static const int MROWS = 6272;     // 32 * 196
static const int CDIM  = 768;
static const int NDIM  = 2304;     // 3 * 768
static const int TT    = 10;
static const int RRK   = 16;

// ---------------- device scratch (static allocation is allowed) --------------
__device__ float g_sumsq[40];                    // [Aq(10) Bq(10) Av(10) Bv(10)]
__device__ float g_scale[2][10];                 // [q, v] per-task fused scales
__device__ float g_Wc[2304u * 768u];             // W_qkv + LoRA deltas, tf32-rounded
__device__ float g_x [6272u * 768u];             // x, tf32-rounded

// ---------------- helpers ----------------------------------------------------
__device__ __forceinline__ uint32_t smem_to_u32(const void* smem_ptr) {
    uint32_t addr;
    asm("{ .reg .u64 tmp; cvta.to.shared.u64 tmp, %1; cvt.u32.u64 %0, tmp; }"
        : "=r"(addr) : "l"(smem_ptr));
    return addr;
}

#define CP_ASYNC16(dst, src) \
    asm volatile("cp.async.cg.shared.global [%0], [%1], 16;" :: "r"((uint32_t)(dst)), "l"(src) : "memory")

#define CP_COMMIT() asm volatile("cp.async.commit_group;" ::: "memory")
#define CP_WAIT(n)  asm volatile("cp.async.wait_group %0;" :: "n"(n) : "memory")

__device__ __forceinline__ float ldsf(uint32_t a) {
    float v;
    asm volatile("ld.shared.f32 %0, [%1];" : "=f"(v) : "r"(a));
    return v;
}

__device__ __forceinline__ float tf32_rnd(float x) {
    float y;
    asm("cvt.rna.tf32.f32 %0, %1;" : "=f"(y) : "f"(x));
    return y;
}

// m16n8k8 tf32 mma (baseline PTX feature, works on compute_103 virtual arch)
__device__ __forceinline__ void mma8(float* c, const float* a, const float* b) {
    const uint32_t* A = reinterpret_cast<const uint32_t*>(a);
    const uint32_t* B = reinterpret_cast<const uint32_t*>(b);
    asm volatile(
        "mma.sync.aligned.m16n8k8.row.col.f32.tf32.tf32.f32 "
        "{%0,%1,%2,%3}, {%4,%5,%6,%7}, {%8,%9}, {%0,%1,%2,%3};"
        : "+f"(c[0]), "+f"(c[1]), "+f"(c[2]), "+f"(c[3])
        : "r"(A[0]), "r"(A[1]), "r"(A[2]), "r"(A[3]), "r"(B[0]), "r"(B[1]));
}

// ---------------- prologue kernels -------------------------------------------

// grid 40 x 256: squared Frobenius norms of each [16,768] / [768,16] matrix
__global__ void norms_kernel(const float* __restrict__ Aq, const float* __restrict__ Bq,
                             const float* __restrict__ Av, const float* __restrict__ Bv) {
    const float* mats[4] = {Aq, Bq, Av, Bv};
    int mi = blockIdx.x / 10;
    int t  = blockIdx.x % 10;
    const float* p = mats[mi] + (size_t)t * (RRK * CDIM);
    float s = 0.f;
    for (int i = threadIdx.x; i < RRK * CDIM; i += 256) {
        float v = p[i];
        s += v * v;
    }
    __shared__ float red[256];
    red[threadIdx.x] = s;
    __syncthreads();
    for (int st = 128; st > 0; st >>= 1) {
        if (threadIdx.x < st) red[threadIdx.x] += red[threadIdx.x + st];
        __syncthreads();
    }
    if (threadIdx.x == 0) g_sumsq[blockIdx.x] = red[0];
}

// 1 x 32: softmax gates fused with 1/(||A||*||B||)
__global__ void scales_kernel(const float* __restrict__ lq, const float* __restrict__ lv) {
    if (threadIdx.x != 0) return;
    for (int b = 0; b < 2; b++) {
        const float* l = b ? lv : lq;
        float mx = -1e30f;
        for (int t = 0; t < TT; t++) mx = fmaxf(mx, l[t] / TAU_F);
        float e[TT], sum = 0.f;
        for (int t = 0; t < TT; t++) { e[t] = expf(l[t] / TAU_F - mx); sum += e[t]; }
        for (int t = 0; t < TT; t++) {
            float sa = g_sumsq[b * 20 + t];
            float sb = g_sumsq[b * 20 + 10 + t];
            g_scale[b][t] = (e[t] / sum) * rsqrtf(sa * sb);
        }
    }
}

// grid (12, 36) x 256: g_Wc = tf32_round(W_qkv + LoRA deltas)
__global__ void build_wc_kernel(const float* __restrict__ W,
                                const float* __restrict__ Aq, const float* __restrict__ Bq,
                                const float* __restrict__ Av, const float* __restrict__ Bv) {
    int i0 = blockIdx.x * 64;      // input-dim tile (0..767)
    int o0 = blockIdx.y * 64;      // output-dim tile (0..2303)
    int band = o0 / CDIM;          // 0 = q-rows, 1 = k-rows (copy), 2 = v-rows
    int tid = threadIdx.x;

    if (band == 1) {               // plain copy + tf32 round
        for (int u = 0; u < 16; u++) {
            int e = tid + u * 256;
            int oo = e >> 6, ii = e & 63;
            size_t idx = (size_t)(o0 + oo) * CDIM + i0 + ii;
            g_Wc[idx] = tf32_rnd(W[idx]);
        }
        return;
    }

    const float* A  = band ? Av : Aq;
    const float* Bm = band ? Bv : Bq;
    const float* sc = g_scale[band ? 1 : 0];
    int lo0 = (band == 2) ? (o0 - 2 * CDIM) : o0;   // local row within [0,768)

    __shared__ float sA[RRK][64];
    __shared__ float sB[64][RRK];

    int to = tid >> 4, ti = tid & 15;
    float acc[4][4] = {};

    for (int t = 0; t < TT; t++) {
        __syncthreads();
        float s = sc[t];
        #pragma unroll
        for (int u = 0; u < 4; u++) {
            int e = tid + u * 256;
            int r = e >> 6, ii = e & 63;
            sA[r][ii] = A[((size_t)t * RRK + r) * CDIM + i0 + ii];
        }
        #pragma unroll
        for (int u = 0; u < 4; u++) {
            int e = tid + u * 256;
            int oo = e >> 4, r = e & 15;
            sB[oo][r] = Bm[((size_t)t * CDIM + lo0 + oo) * RRK + r] * s;
        }
        __syncthreads();
        #pragma unroll
        for (int r = 0; r < RRK; r++) {
            float a[4], b[4];
            #pragma unroll
            for (int x = 0; x < 4; x++) { a[x] = sA[r][ti * 4 + x]; b[x] = sB[to * 4 + x][r]; }
            #pragma unroll
            for (int x = 0; x < 4; x++)
                #pragma unroll
                for (int y = 0; y < 4; y++)
                    acc[x][y] += b[x] * a[y];
        }
    }

    #pragma unroll
    for (int x = 0; x < 4; x++) {
        size_t row = (size_t)(o0 + to * 4 + x);
        #pragma unroll
        for (int y = 0; y < 4; y++) {
            size_t idx = row * CDIM + i0 + ti * 4 + y;
            g_Wc[idx] = tf32_rnd(W[idx] + acc[x][y]);
        }
    }
}

// grid 4704 x 256: g_x = tf32_round(x)   (round-to-nearest, beats HW truncation)
__global__ void round_x_kernel(const float* __restrict__ x) {
    const int n4 = MROWS * CDIM / 4;
    for (int i = blockIdx.x * blockDim.x + threadIdx.x; i < n4; i += gridDim.x * blockDim.x) {
        float4 v = ((const float4*)x)[i];
        v.x = tf32_rnd(v.x); v.y = tf32_rnd(v.y); v.z = tf32_rnd(v.z); v.w = tf32_rnd(v.w);
        ((float4*)g_x)[i] = v;
    }
}

// ---------------- main GEMM: out = g_x @ g_Wc^T + bias -----------------------
// CTA tile 128(M) x 128(N), BK=32 tf32, 3-stage cp.async ring, mma.sync m16n8k8.
// 256 threads = 8 warps in 2(M) x 4(N); warp tile 64x32 = 4x4 m16n8 tiles.

static const int KT = CDIM / 32;          // 24 k-tiles
static const int STAGE_BYTES = 32768;     // A 16KB + B 16KB
static const int SMEM_DYN = 3 * STAGE_BYTES;

__global__ void __launch_bounds__(256, 2)
gemm_kernel(const float* __restrict__ bias, float* __restrict__ out) {
    extern __shared__ char smem[];
    const uint32_t sbase = smem_to_u32(smem);

    const int tid = threadIdx.x;
    const int wid = tid >> 5, lid = tid & 31;
    const int lr  = lid >> 2, lc = lid & 3;          // mma fragment coords
    const int n0  = blockIdx.x * 128;
    const int m0  = blockIdx.y * 128;
    const int mw  = (wid & 1) * 64;
    const int nw  = (wid >> 1) * 32;

    const float* gA = g_x  + (size_t)m0 * CDIM;
    const float* gB = g_Wc + (size_t)n0 * CDIM;

    // loader mapping: 256 thr x 4 iters -> 1024 chunks of 16B per 128x32 tile
    const int lrow = tid >> 3;        // 0..31 (+q*32)
    const int lc8  = tid & 7;         // 16B chunk within 128B row

    auto load_stage = [&](int s) {
        uint32_t st = sbase + (uint32_t)(s % 3) * STAGE_BYTES;
        int k0 = s * 32;
        #pragma unroll
        for (int q = 0; q < 4; q++) {
            int row = lrow + q * 32;
            uint32_t off = (uint32_t)row * 128 + (uint32_t)(lc8 ^ (row & 7)) * 16;
            CP_ASYNC16(st + off,         gA + (size_t)row * CDIM + k0 + lc8 * 4);
            CP_ASYNC16(st + 16384 + off, gB + (size_t)row * CDIM + k0 + lc8 * 4);
        }
    };

    float acc[4][4][4] = {};

    load_stage(0); CP_COMMIT();
    load_stage(1); CP_COMMIT();

    const uint32_t xr = (uint32_t)lr * 16;          // swizzle XOR (distributes over <<4)

    for (int i = 0; i < KT; ++i) {
        CP_WAIT(1);                                  // stage i resident
        __syncthreads();                             // all warps done with slot (i+2)%3
        if (i + 2 < KT) load_stage(i + 2);
        CP_COMMIT();                                 // keep group bookkeeping uniform

        uint32_t sA = sbase + (uint32_t)(i % 3) * STAGE_BYTES;
        uint32_t sB = sA + 16384;

        #pragma unroll
        for (int ks = 0; ks < 4; ks++) {
            uint32_t g0 = ((uint32_t)(2 * ks)     * 16) ^ xr;
            uint32_t g1 = ((uint32_t)(2 * ks + 1) * 16) ^ xr;

            float a[4][4];
            #pragma unroll
            for (int mt = 0; mt < 4; mt++) {
                uint32_t base = sA + (uint32_t)(mw + mt * 16 + lr) * 128 + (uint32_t)lc * 4;
                a[mt][0] = ldsf(base + g0);
                a[mt][1] = ldsf(base + 8 * 128 + g0);
                a[mt][2] = ldsf(base + g1);
                a[mt][3] = ldsf(base + 8 * 128 + g1);
            }
            float b[4][2];
            #pragma unroll
            for (int nt = 0; nt < 4; nt++) {
                uint32_t base = sB + (uint32_t)(nw + nt * 8 + lr) * 128 + (uint32_t)lc * 4;
                b[nt][0] = ldsf(base + g0);
                b[nt][1] = ldsf(base + g1);
            }
            #pragma unroll
            for (int mt = 0; mt < 4; mt++)
                #pragma unroll
                for (int nt = 0; nt < 4; nt++)
                    mma8(acc[mt][nt], a[mt], b[nt]);
        }
    }

    // epilogue: regs -> gmem with bias, float2 stores
    #pragma unroll
    for (int mt = 0; mt < 4; mt++) {
        #pragma unroll
        for (int nt = 0; nt < 4; nt++) {
            int m = m0 + mw + mt * 16 + lr;
            int n = n0 + nw + nt * 8 + lc * 2;
            float2 bb = *(const float2*)(bias + n);
            float2 v0 = make_float2(acc[mt][nt][0] + bb.x, acc[mt][nt][1] + bb.y);
            float2 v1 = make_float2(acc[mt][nt][2] + bb.x, acc[mt][nt][3] + bb.y);
            *(float2*)(out + (size_t)m * NDIM + n)       = v0;
            *(float2*)(out + (size_t)(m + 8) * NDIM + n) = v1;
        }
    }
}

// ---------------- launch ------------------------------------------------------
extern "C" void kernel_launch(void* const* d_in, const int* in_sizes, int n_in,
                              void* d_out, int out_size) {
    const float* x  = (const float*)d_in[0];
    const float* W  = (const float*)d_in[1];
    const float* b  = (const float*)d_in[2];
    const float* Aq = (const float*)d_in[3];
    const float* Bq = (const float*)d_in[4];
    const float* Av = (const float*)d_in[5];
    const float* Bv = (const float*)d_in[6];
    const float* lq = (const float*)d_in[7];
    const float* lv = (const float*)d_in[8];
    float* out = (float*)d_out;

    norms_kernel<<<40, 256>>>(Aq, Bq, Av, Bv);
    scales_kernel<<<1, 32>>>(lq, lv);
    build_wc_kernel<<<dim3(12, 36), 256>>>(W, Aq, Bq, Av, Bv);
    round_x_kernel<<<4704, 256>>>(x);

    cudaFuncSetAttribute(gemm_kernel, cudaFuncAttributeMaxDynamicSharedMemorySize, SMEM_DYN);
    gemm_kernel<<<dim3(NDIM / 128, MROWS / 128), 256, SMEM_DYN>>>(b, out);
}

// round 6
// speedup vs baseline: 1.0528x; 1.0528x over previous
#include <cuda_runtime.h>
#include <cstdint>

#define TAU_F 0.5f

static const int MROWS = 6272;     // 32 * 196
static const int CDIM  = 768;
static const int NDIM  = 2304;     // 3 * 768
static const int TT    = 10;
static const int RRK   = 16;

// ---------------- device scratch (static allocation is allowed) --------------
__device__ float g_sumsq[40];                    // [Aq(10) Bq(10) Av(10) Bv(10)]
__device__ float g_scale[2][10];                 // [q, v] per-task fused scales
__device__ float g_Wc[2304u * 768u];             // W_qkv + LoRA deltas, tf32-rounded
__device__ float g_x [6272u * 768u];             // x, tf32-rounded

// ---------------- helpers ----------------------------------------------------
__device__ __forceinline__ uint32_t smem_to_u32(const void* smem_ptr) {
    uint32_t addr;
    asm("{ .reg .u64 tmp; cvta.to.shared.u64 tmp, %1; cvt.u32.u64 %0, tmp; }"
        : "=r"(addr) : "l"(smem_ptr));
    return addr;
}

#define CP_ASYNC16(dst, src) \
    asm volatile("cp.async.cg.shared.global [%0], [%1], 16;" :: "r"((uint32_t)(dst)), "l"(src) : "memory")

#define CP_COMMIT() asm volatile("cp.async.commit_group;" ::: "memory")
#define CP_WAIT(n)  asm volatile("cp.async.wait_group %0;" :: "n"(n) : "memory")

__device__ __forceinline__ float tf32_rnd(float x) {
    float y;
    asm("cvt.rna.tf32.f32 %0, %1;" : "=f"(y) : "f"(x));
    return y;
}

// ldmatrix x4: four 8x8 b16 matrices == four 8x4 fp32 blocks, whose register
// distribution (thread t -> fp32 element (t/4, t%4)) is exactly the
// m16n8k8.tf32 fragment layout. Baseline PTX (sm_75+), fine on compute_103.
__device__ __forceinline__ void ldsm4(uint32_t* r, uint32_t addr) {
    asm volatile("ldmatrix.sync.aligned.m8n8.x4.shared.b16 {%0,%1,%2,%3}, [%4];"
        : "=r"(r[0]), "=r"(r[1]), "=r"(r[2]), "=r"(r[3]) : "r"(addr));
}

// m16n8k8 tf32 mma (baseline PTX feature)
__device__ __forceinline__ void mma8(float* c, const uint32_t* A, const uint32_t* B) {
    asm volatile(
        "mma.sync.aligned.m16n8k8.row.col.f32.tf32.tf32.f32 "
        "{%0,%1,%2,%3}, {%4,%5,%6,%7}, {%8,%9}, {%0,%1,%2,%3};"
        : "+f"(c[0]), "+f"(c[1]), "+f"(c[2]), "+f"(c[3])
        : "r"(A[0]), "r"(A[1]), "r"(A[2]), "r"(A[3]), "r"(B[0]), "r"(B[1]));
}

// ---------------- prologue kernels -------------------------------------------

// grid 40 x 256: squared Frobenius norms of each [16,768] / [768,16] matrix
__global__ void norms_kernel(const float* __restrict__ Aq, const float* __restrict__ Bq,
                             const float* __restrict__ Av, const float* __restrict__ Bv) {
    const float* mats[4] = {Aq, Bq, Av, Bv};
    int mi = blockIdx.x / 10;
    int t  = blockIdx.x % 10;
    const float* p = mats[mi] + (size_t)t * (RRK * CDIM);
    float s = 0.f;
    for (int i = threadIdx.x; i < RRK * CDIM; i += 256) {
        float v = p[i];
        s += v * v;
    }
    __shared__ float red[256];
    red[threadIdx.x] = s;
    __syncthreads();
    for (int st = 128; st > 0; st >>= 1) {
        if (threadIdx.x < st) red[threadIdx.x] += red[threadIdx.x + st];
        __syncthreads();
    }
    if (threadIdx.x == 0) g_sumsq[blockIdx.x] = red[0];
}

// 1 x 32: softmax gates fused with 1/(||A||*||B||)
__global__ void scales_kernel(const float* __restrict__ lq, const float* __restrict__ lv) {
    if (threadIdx.x != 0) return;
    for (int b = 0; b < 2; b++) {
        const float* l = b ? lv : lq;
        float mx = -1e30f;
        for (int t = 0; t < TT; t++) mx = fmaxf(mx, l[t] / TAU_F);
        float e[TT], sum = 0.f;
        for (int t = 0; t < TT; t++) { e[t] = expf(l[t] / TAU_F - mx); sum += e[t]; }
        for (int t = 0; t < TT; t++) {
            float sa = g_sumsq[b * 20 + t];
            float sb = g_sumsq[b * 20 + 10 + t];
            g_scale[b][t] = (e[t] / sum) * rsqrtf(sa * sb);
        }
    }
}

// grid (12, 36) x 256: g_Wc = tf32_round(W_qkv + LoRA deltas)
__global__ void build_wc_kernel(const float* __restrict__ W,
                                const float* __restrict__ Aq, const float* __restrict__ Bq,
                                const float* __restrict__ Av, const float* __restrict__ Bv) {
    int i0 = blockIdx.x * 64;      // input-dim tile (0..767)
    int o0 = blockIdx.y * 64;      // output-dim tile (0..2303)
    int band = o0 / CDIM;          // 0 = q-rows, 1 = k-rows (copy), 2 = v-rows
    int tid = threadIdx.x;

    if (band == 1) {               // plain copy + tf32 round
        for (int u = 0; u < 16; u++) {
            int e = tid + u * 256;
            int oo = e >> 6, ii = e & 63;
            size_t idx = (size_t)(o0 + oo) * CDIM + i0 + ii;
            g_Wc[idx] = tf32_rnd(W[idx]);
        }
        return;
    }

    const float* A  = band ? Av : Aq;
    const float* Bm = band ? Bv : Bq;
    const float* sc = g_scale[band ? 1 : 0];
    int lo0 = (band == 2) ? (o0 - 2 * CDIM) : o0;   // local row within [0,768)

    __shared__ float sA[RRK][64];
    __shared__ float sB[64][RRK];

    int to = tid >> 4, ti = tid & 15;
    float acc[4][4] = {};

    for (int t = 0; t < TT; t++) {
        __syncthreads();
        float s = sc[t];
        #pragma unroll
        for (int u = 0; u < 4; u++) {
            int e = tid + u * 256;
            int r = e >> 6, ii = e & 63;
            sA[r][ii] = A[((size_t)t * RRK + r) * CDIM + i0 + ii];
        }
        #pragma unroll
        for (int u = 0; u < 4; u++) {
            int e = tid + u * 256;
            int oo = e >> 4, r = e & 15;
            sB[oo][r] = Bm[((size_t)t * CDIM + lo0 + oo) * RRK + r] * s;
        }
        __syncthreads();
        #pragma unroll
        for (int r = 0; r < RRK; r++) {
            float a[4], b[4];
            #pragma unroll
            for (int x = 0; x < 4; x++) { a[x] = sA[r][ti * 4 + x]; b[x] = sB[to * 4 + x][r]; }
            #pragma unroll
            for (int x = 0; x < 4; x++)
                #pragma unroll
                for (int y = 0; y < 4; y++)
                    acc[x][y] += b[x] * a[y];
        }
    }

    #pragma unroll
    for (int x = 0; x < 4; x++) {
        size_t row = (size_t)(o0 + to * 4 + x);
        #pragma unroll
        for (int y = 0; y < 4; y++) {
            size_t idx = row * CDIM + i0 + ti * 4 + y;
            g_Wc[idx] = tf32_rnd(W[idx] + acc[x][y]);
        }
    }
}

// grid 4704 x 256: g_x = tf32_round(x)   (round-to-nearest, beats HW truncation)
__global__ void round_x_kernel(const float* __restrict__ x) {
    const int n4 = MROWS * CDIM / 4;
    for (int i = blockIdx.x * blockDim.x + threadIdx.x; i < n4; i += gridDim.x * blockDim.x) {
        float4 v = ((const float4*)x)[i];
        v.x = tf32_rnd(v.x); v.y = tf32_rnd(v.y); v.z = tf32_rnd(v.z); v.w = tf32_rnd(v.w);
        ((float4*)g_x)[i] = v;
    }
}

// ---------------- main GEMM: out = g_x @ g_Wc^T + bias -----------------------
// CTA tile 128(M) x 256(N), BK=32 tf32, 3-stage cp.async ring.
// 256 threads = 8 warps in 2(M) x 4(N); warp tile 64x64 = 4x8 m16n8 tiles.
// Operand fetch via ldmatrix.x4 (b16-view trick), XOR-swizzled smem.

static const int KT = CDIM / 32;          // 24 k-tiles
static const int STAGE_BYTES = 49152;     // A 16KB + B 32KB
static const int SMEM_DYN = 3 * STAGE_BYTES;

__global__ void __launch_bounds__(256, 1)
gemm_kernel(const float* __restrict__ bias, float* __restrict__ out) {
    extern __shared__ char smem[];
    const uint32_t sbase = smem_to_u32(smem);

    const int tid = threadIdx.x;
    const int wid = tid >> 5, lid = tid & 31;
    const int lr  = lid >> 2, lc = lid & 3;          // mma fragment coords
    const int sub = lid >> 3, r8 = lid & 7;          // ldmatrix coords
    const int n0  = blockIdx.x * 256;
    const int m0  = blockIdx.y * 128;
    const int mw  = (wid >> 2) * 64;                 // 2 M-halves
    const int nw  = (wid & 3) * 64;                  // 4 N-quarters

    const float* gA = g_x  + (size_t)m0 * CDIM;
    const float* gB = g_Wc + (size_t)n0 * CDIM;

    // loader mapping: 256 thr; A 1024 granules (4/thr), B 2048 granules (8/thr)
    const int lrow = tid >> 3;        // 0..31
    const int lc8  = tid & 7;         // 16B chunk within 128B row

    auto load_stage = [&](int s) {
        uint32_t st = sbase + (uint32_t)(s % 3) * STAGE_BYTES;
        int k0 = s * 32;
        #pragma unroll
        for (int q = 0; q < 4; q++) {             // A: 128 rows
            int row = lrow + q * 32;
            uint32_t off = (uint32_t)row * 128 + (uint32_t)(lc8 ^ (row & 7)) * 16;
            CP_ASYNC16(st + off, gA + (size_t)row * CDIM + k0 + lc8 * 4);
        }
        #pragma unroll
        for (int q = 0; q < 8; q++) {             // B: 256 rows
            int row = lrow + q * 32;
            uint32_t off = (uint32_t)row * 128 + (uint32_t)(lc8 ^ (row & 7)) * 16;
            CP_ASYNC16(st + 16384 + off, gB + (size_t)row * CDIM + k0 + lc8 * 4);
        }
    };

    // ldmatrix per-thread row terms (byte offsets within a stage)
    // A fragments: sub0: m rows +0..7 (k lo), sub1: +8 (k lo), sub2: +0..7 (k hi), sub3: +8 (k hi)
    const int kgA = sub >> 1;
    uint32_t rowTermA[4];
    #pragma unroll
    for (int mt = 0; mt < 4; mt++)
        rowTermA[mt] = (uint32_t)(mw + mt * 16 + (sub & 1) * 8 + r8) * 128;
    // B fragments (pack 2 n-tiles per x4): sub0: nt even rows (k lo), sub1: nt even (k hi),
    //                                      sub2: nt odd (k lo),  sub3: nt odd (k hi)
    const int kgB = sub & 1;
    uint32_t rowTermB[4];
    #pragma unroll
    for (int p = 0; p < 4; p++)
        rowTermB[p] = 16384u + (uint32_t)(nw + (p * 2 + (sub >> 1)) * 8 + r8) * 128;

    float acc[4][8][4] = {};

    load_stage(0); CP_COMMIT();
    load_stage(1); CP_COMMIT();

    for (int i = 0; i < KT; ++i) {
        CP_WAIT(1);                                  // stage i resident
        __syncthreads();                             // all warps done with slot (i+2)%3
        if (i + 2 < KT) load_stage(i + 2);
        CP_COMMIT();                                 // keep group bookkeeping uniform

        uint32_t st = sbase + (uint32_t)(i % 3) * STAGE_BYTES;

        #pragma unroll
        for (int ks = 0; ks < 4; ks++) {
            uint32_t gA_ = (uint32_t)(((2 * ks + kgA) ^ r8) * 16);
            uint32_t gB_ = (uint32_t)(((2 * ks + kgB) ^ r8) * 16);

            uint32_t a[4][4];
            #pragma unroll
            for (int mt = 0; mt < 4; mt++)
                ldsm4(a[mt], st + rowTermA[mt] + gA_);
            uint32_t b[4][4];                        // b[p] = {b0,b1 of nt=2p; b0,b1 of nt=2p+1}
            #pragma unroll
            for (int p = 0; p < 4; p++)
                ldsm4(b[p], st + rowTermB[p] + gB_);

            #pragma unroll
            for (int mt = 0; mt < 4; mt++)
                #pragma unroll
                for (int nt = 0; nt < 8; nt++)
                    mma8(acc[mt][nt], a[mt], &b[nt >> 1][(nt & 1) * 2]);
        }
    }

    // epilogue: regs -> gmem with bias, float2 stores
    float2 bb[8];
    #pragma unroll
    for (int nt = 0; nt < 8; nt++)
        bb[nt] = *(const float2*)(bias + n0 + nw + nt * 8 + lc * 2);

    #pragma unroll
    for (int mt = 0; mt < 4; mt++) {
        #pragma unroll
        for (int nt = 0; nt < 8; nt++) {
            int m = m0 + mw + mt * 16 + lr;
            int n = n0 + nw + nt * 8 + lc * 2;
            float2 v0 = make_float2(acc[mt][nt][0] + bb[nt].x, acc[mt][nt][1] + bb[nt].y);
            float2 v1 = make_float2(acc[mt][nt][2] + bb[nt].x, acc[mt][nt][3] + bb[nt].y);
            *(float2*)(out + (size_t)m * NDIM + n)       = v0;
            *(float2*)(out + (size_t)(m + 8) * NDIM + n) = v1;
        }
    }
}

// ---------------- launch ------------------------------------------------------
extern "C" void kernel_launch(void* const* d_in, const int* in_sizes, int n_in,
                              void* d_out, int out_size) {
    const float* x  = (const float*)d_in[0];
    const float* W  = (const float*)d_in[1];
    const float* b  = (const float*)d_in[2];
    const float* Aq = (const float*)d_in[3];
    const float* Bq = (const float*)d_in[4];
    const float* Av = (const float*)d_in[5];
    const float* Bv = (const float*)d_in[6];
    const float* lq = (const float*)d_in[7];
    const float* lv = (const float*)d_in[8];
    float* out = (float*)d_out;

    norms_kernel<<<40, 256>>>(Aq, Bq, Av, Bv);
    scales_kernel<<<1, 32>>>(lq, lv);
    build_wc_kernel<<<dim3(12, 36), 256>>>(W, Aq, Bq, Av, Bv);
    round_x_kernel<<<4704, 256>>>(x);

    cudaFuncSetAttribute(gemm_kernel, cudaFuncAttributeMaxDynamicSharedMemorySize, SMEM_DYN);
    gemm_kernel<<<dim3(NDIM / 256, MROWS / 128), 256, SMEM_DYN>>>(b, out);
}

// round 8
// speedup vs baseline: 1.5992x; 1.5190x over previous
#include <cuda_runtime.h>
#include <cuda_fp16.h>
#include <cstdint>

#define TAU_F 0.5f

static const int MROWS = 6272;     // 32 * 196
static const int CDIM  = 768;
static const int NDIM  = 2304;     // 3 * 768
static const int TT    = 10;
static const int RRK   = 16;

// ---------------- device scratch (static allocation is allowed) --------------
__device__ float  g_sumsq[40];                   // [Aq(10) Bq(10) Av(10) Bv(10)]
__device__ float  g_scale[2][10];                // [q, v] per-task fused scales
__device__ __half g_Wch[2304u * 768u];           // W_qkv + LoRA deltas, f16-rna
__device__ __half g_xh [6272u * 768u];           // x, f16-rna

// ---------------- helpers ----------------------------------------------------
__device__ __forceinline__ uint32_t smem_to_u32(const void* smem_ptr) {
    uint32_t addr;
    asm("{ .reg .u64 tmp; cvta.to.shared.u64 tmp, %1; cvt.u32.u64 %0, tmp; }"
        : "=r"(addr) : "l"(smem_ptr));
    return addr;
}

#define CP_ASYNC16(dst, src) \
    asm volatile("cp.async.cg.shared.global [%0], [%1], 16;" :: "r"((uint32_t)(dst)), "l"(src) : "memory")

#define CP_COMMIT() asm volatile("cp.async.commit_group;" ::: "memory")
#define CP_WAIT(n)  asm volatile("cp.async.wait_group %0;" :: "n"(n) : "memory")

// ldmatrix x4 (baseline PTX sm_75+)
__device__ __forceinline__ void ldsm4(uint32_t* r, uint32_t addr) {
    asm volatile("ldmatrix.sync.aligned.m8n8.x4.shared.b16 {%0,%1,%2,%3}, [%4];"
        : "=r"(r[0]), "=r"(r[1]), "=r"(r[2]), "=r"(r[3]) : "r"(addr));
}

// m16n8k16 f16 mma, f32 accumulate (baseline PTX sm_80+): 4096 FLOP/instr
__device__ __forceinline__ void mma16(float* c, const uint32_t* A, const uint32_t* B) {
    asm volatile(
        "mma.sync.aligned.m16n8k16.row.col.f32.f16.f16.f32 "
        "{%0,%1,%2,%3}, {%4,%5,%6,%7}, {%8,%9}, {%0,%1,%2,%3};"
        : "+f"(c[0]), "+f"(c[1]), "+f"(c[2]), "+f"(c[3])
        : "r"(A[0]), "r"(A[1]), "r"(A[2]), "r"(A[3]), "r"(B[0]), "r"(B[1]));
}

// ---------------- prologue kernels -------------------------------------------

// grid 40 x 256: squared Frobenius norms of each [16,768] / [768,16] matrix
__global__ void norms_kernel(const float* __restrict__ Aq, const float* __restrict__ Bq,
                             const float* __restrict__ Av, const float* __restrict__ Bv) {
    const float* mats[4] = {Aq, Bq, Av, Bv};
    int mi = blockIdx.x / 10;
    int t  = blockIdx.x % 10;
    const float* p = mats[mi] + (size_t)t * (RRK * CDIM);
    float s = 0.f;
    for (int i = threadIdx.x; i < RRK * CDIM; i += 256) {
        float v = p[i];
        s += v * v;
    }
    __shared__ float red[256];
    red[threadIdx.x] = s;
    __syncthreads();
    for (int st = 128; st > 0; st >>= 1) {
        if (threadIdx.x < st) red[threadIdx.x] += red[threadIdx.x + st];
        __syncthreads();
    }
    if (threadIdx.x == 0) g_sumsq[blockIdx.x] = red[0];
}

// 1 x 32: softmax gates fused with 1/(||A||*||B||)
__global__ void scales_kernel(const float* __restrict__ lq, const float* __restrict__ lv) {
    if (threadIdx.x != 0) return;
    for (int b = 0; b < 2; b++) {
        const float* l = b ? lv : lq;
        float mx = -1e30f;
        for (int t = 0; t < TT; t++) mx = fmaxf(mx, l[t] / TAU_F);
        float e[TT], sum = 0.f;
        for (int t = 0; t < TT; t++) { e[t] = expf(l[t] / TAU_F - mx); sum += e[t]; }
        for (int t = 0; t < TT; t++) {
            float sa = g_sumsq[b * 20 + t];
            float sb = g_sumsq[b * 20 + 10 + t];
            g_scale[b][t] = (e[t] / sum) * rsqrtf(sa * sb);
        }
    }
}

// grid (12, 36) x 256: g_Wch = f16_rn(W_qkv + LoRA deltas)
__global__ void build_wc_kernel(const float* __restrict__ W,
                                const float* __restrict__ Aq, const float* __restrict__ Bq,
                                const float* __restrict__ Av, const float* __restrict__ Bv) {
    int i0 = blockIdx.x * 64;      // input-dim tile (0..767)
    int o0 = blockIdx.y * 64;      // output-dim tile (0..2303)
    int band = o0 / CDIM;          // 0 = q-rows, 1 = k-rows (copy), 2 = v-rows
    int tid = threadIdx.x;

    if (band == 1) {               // plain copy + f16 round
        for (int u = 0; u < 16; u++) {
            int e = tid + u * 256;
            int oo = e >> 6, ii = e & 63;
            size_t idx = (size_t)(o0 + oo) * CDIM + i0 + ii;
            g_Wch[idx] = __float2half_rn(W[idx]);
        }
        return;
    }

    const float* A  = band ? Av : Aq;
    const float* Bm = band ? Bv : Bq;
    const float* sc = g_scale[band ? 1 : 0];
    int lo0 = (band == 2) ? (o0 - 2 * CDIM) : o0;   // local row within [0,768)

    __shared__ float sA[RRK][64];
    __shared__ float sB[64][RRK];

    int to = tid >> 4, ti = tid & 15;
    float acc[4][4] = {};

    for (int t = 0; t < TT; t++) {
        __syncthreads();
        float s = sc[t];
        #pragma unroll
        for (int u = 0; u < 4; u++) {
            int e = tid + u * 256;
            int r = e >> 6, ii = e & 63;
            sA[r][ii] = A[((size_t)t * RRK + r) * CDIM + i0 + ii];
        }
        #pragma unroll
        for (int u = 0; u < 4; u++) {
            int e = tid + u * 256;
            int oo = e >> 4, r = e & 15;
            sB[oo][r] = Bm[((size_t)t * CDIM + lo0 + oo) * RRK + r] * s;
        }
        __syncthreads();
        #pragma unroll
        for (int r = 0; r < RRK; r++) {
            float a[4], b[4];
            #pragma unroll
            for (int x = 0; x < 4; x++) { a[x] = sA[r][ti * 4 + x]; b[x] = sB[to * 4 + x][r]; }
            #pragma unroll
            for (int x = 0; x < 4; x++)
                #pragma unroll
                for (int y = 0; y < 4; y++)
                    acc[x][y] += b[x] * a[y];
        }
    }

    #pragma unroll
    for (int x = 0; x < 4; x++) {
        size_t row = (size_t)(o0 + to * 4 + x);
        #pragma unroll
        for (int y = 0; y < 4; y++) {
            size_t idx = row * CDIM + i0 + ti * 4 + y;
            g_Wch[idx] = __float2half_rn(W[idx] + acc[x][y]);
        }
    }
}

// grid 4704 x 256: g_xh = f16_rn(x)
__global__ void cvt_x_kernel(const float* __restrict__ x) {
    const int n4 = MROWS * CDIM / 4;
    for (int i = blockIdx.x * blockDim.x + threadIdx.x; i < n4; i += gridDim.x * blockDim.x) {
        float4 v = ((const float4*)x)[i];
        __half2 h0 = __floats2half2_rn(v.x, v.y);
        __half2 h1 = __floats2half2_rn(v.z, v.w);
        uint2 pk;
        pk.x = *reinterpret_cast<uint32_t*>(&h0);
        pk.y = *reinterpret_cast<uint32_t*>(&h1);
        ((uint2*)g_xh)[i] = pk;
    }
}

// ---------------- main GEMM: out = g_xh @ g_Wch^T + bias ---------------------
// CTA tile 128(M) x 256(N), BK=64 f16, 3-stage cp.async ring.
// 256 threads = 8 warps in 2(M) x 4(N); warp tile 64x64 = 4x8 m16n8 tiles.
// Operand fetch via ldmatrix.x4, XOR-swizzled smem rows of 128B (64 halves).

static const int KT = CDIM / 64;          // 12 k-tiles
static const int STAGE_BYTES = 49152;     // A 16KB + B 32KB
static const int SMEM_DYN = 3 * STAGE_BYTES;

__global__ void __launch_bounds__(256, 1)
gemm_kernel(const float* __restrict__ bias, float* __restrict__ out) {
    extern __shared__ char smem[];
    const uint32_t sbase = smem_to_u32(smem);

    const int tid = threadIdx.x;
    const int wid = tid >> 5, lid = tid & 31;
    const int lr  = lid >> 2, lc = lid & 3;          // mma fragment coords
    const int sub = lid >> 3, r8 = lid & 7;          // ldmatrix coords
    const int n0  = blockIdx.x * 256;
    const int m0  = blockIdx.y * 128;
    const int mw  = (wid >> 2) * 64;                 // 2 M-halves
    const int nw  = (wid & 3) * 64;                  // 4 N-quarters

    const __half* gA = g_xh  + (size_t)m0 * CDIM;
    const __half* gB = g_Wch + (size_t)n0 * CDIM;

    // loader mapping: 256 thr; A 1024 granules (4/thr), B 2048 granules (8/thr)
    const int lrow = tid >> 3;        // 0..31
    const int lc8  = tid & 7;         // 16B granule within 128B row

    auto load_stage = [&](int s) {
        uint32_t st = sbase + (uint32_t)(s % 3) * STAGE_BYTES;
        int k0 = s * 64;              // in halves
        #pragma unroll
        for (int q = 0; q < 4; q++) {             // A: 128 rows
            int row = lrow + q * 32;
            uint32_t off = (uint32_t)row * 128 + (uint32_t)(lc8 ^ (row & 7)) * 16;
            CP_ASYNC16(st + off, gA + (size_t)row * CDIM + k0 + lc8 * 8);
        }
        #pragma unroll
        for (int q = 0; q < 8; q++) {             // B: 256 rows
            int row = lrow + q * 32;
            uint32_t off = (uint32_t)row * 128 + (uint32_t)(lc8 ^ (row & 7)) * 16;
            CP_ASYNC16(st + 16384 + off, gB + (size_t)row * CDIM + k0 + lc8 * 8);
        }
    };

    // ldmatrix per-thread row terms (byte offsets within a stage)
    // A x4 over (m16, k16): sub0:(m0-7,klo) sub1:(m8-15,klo) sub2:(m0-7,khi) sub3:(m8-15,khi)
    const int kgA = sub >> 1;
    uint32_t rowTermA[4];
    #pragma unroll
    for (int mt = 0; mt < 4; mt++)
        rowTermA[mt] = (uint32_t)(mw + mt * 16 + (sub & 1) * 8 + r8) * 128;
    // B x4 over (n16, k16): sub0:(n0-7,klo) sub1:(n0-7,khi) sub2:(n8-15,klo) sub3:(n8-15,khi)
    const int kgB = sub & 1;
    uint32_t rowTermB[4];
    #pragma unroll
    for (int p = 0; p < 4; p++)
        rowTermB[p] = 16384u + (uint32_t)(nw + p * 16 + (sub >> 1) * 8 + r8) * 128;

    float acc[4][8][4] = {};

    load_stage(0); CP_COMMIT();
    load_stage(1); CP_COMMIT();

    for (int i = 0; i < KT; ++i) {
        CP_WAIT(1);                                  // stage i resident
        __syncthreads();                             // all warps done with slot (i+2)%3
        if (i + 2 < KT) load_stage(i + 2);
        CP_COMMIT();                                 // keep group bookkeeping uniform

        uint32_t st = sbase + (uint32_t)(i % 3) * STAGE_BYTES;

        #pragma unroll
        for (int ks = 0; ks < 4; ks++) {             // 4 x k16 chunks per BK=64
            uint32_t gA_ = (uint32_t)(((2 * ks + kgA) ^ r8) * 16);
            uint32_t gB_ = (uint32_t)(((2 * ks + kgB) ^ r8) * 16);

            uint32_t a[4][4];
            #pragma unroll
            for (int mt = 0; mt < 4; mt++)
                ldsm4(a[mt], st + rowTermA[mt] + gA_);
            uint32_t b[4][4];   // b[p] = {b0(nt=2p), b1(nt=2p), b0(nt=2p+1), b1(nt=2p+1)}
            #pragma unroll
            for (int p = 0; p < 4; p++)
                ldsm4(b[p], st + rowTermB[p] + gB_);

            #pragma unroll
            for (int mt = 0; mt < 4; mt++)
                #pragma unroll
                for (int nt = 0; nt < 8; nt++)
                    mma16(acc[mt][nt], a[mt], &b[nt >> 1][(nt & 1) * 2]);
        }
    }

    // epilogue: regs -> gmem with bias, float2 stores
    float2 bb[8];
    #pragma unroll
    for (int nt = 0; nt < 8; nt++)
        bb[nt] = *(const float2*)(bias + n0 + nw + nt * 8 + lc * 2);

    #pragma unroll
    for (int mt = 0; mt < 4; mt++) {
        #pragma unroll
        for (int nt = 0; nt < 8; nt++) {
            int m = m0 + mw + mt * 16 + lr;
            int n = n0 + nw + nt * 8 + lc * 2;
            float2 v0 = make_float2(acc[mt][nt][0] + bb[nt].x, acc[mt][nt][1] + bb[nt].y);
            float2 v1 = make_float2(acc[mt][nt][2] + bb[nt].x, acc[mt][nt][3] + bb[nt].y);
            *(float2*)(out + (size_t)m * NDIM + n)       = v0;
            *(float2*)(out + (size_t)(m + 8) * NDIM + n) = v1;
        }
    }
}

// ---------------- launch ------------------------------------------------------
extern "C" void kernel_launch(void* const* d_in, const int* in_sizes, int n_in,
                              void* d_out, int out_size) {
    const float* x  = (const float*)d_in[0];
    const float* W  = (const float*)d_in[1];
    const float* b  = (const float*)d_in[2];
    const float* Aq = (const float*)d_in[3];
    const float* Bq = (const float*)d_in[4];
    const float* Av = (const float*)d_in[5];
    const float* Bv = (const float*)d_in[6];
    const float* lq = (const float*)d_in[7];
    const float* lv = (const float*)d_in[8];
    float* out = (float*)d_out;

    norms_kernel<<<40, 256>>>(Aq, Bq, Av, Bv);
    scales_kernel<<<1, 32>>>(lq, lv);
    build_wc_kernel<<<dim3(12, 36), 256>>>(W, Aq, Bq, Av, Bv);
    cvt_x_kernel<<<4704, 256>>>(x);

    cudaFuncSetAttribute(gemm_kernel, cudaFuncAttributeMaxDynamicSharedMemorySize, SMEM_DYN);
    gemm_kernel<<<dim3(NDIM / 256, MROWS / 128), 256, SMEM_DYN>>>(b, out);
}